// round 5
// baseline (speedup 1.0000x reference)
#include <cuda_runtime.h>
#include <cuda_bf16.h>
#include <cstdint>
#include <cstddef>

#define H_DIM 4096
#define I_DIM 14336
#define M_DIM 1024

__device__ __align__(1024) float g_gate_eff[(size_t)I_DIM * H_DIM];
__device__ __align__(1024) float g_up_eff  [(size_t)I_DIM * H_DIM];
__device__ __align__(1024) float g_down_eff[(size_t)H_DIM * I_DIM];
__device__ __align__(1024) float g_a       [(size_t)M_DIM * I_DIM];
__device__ __align__(1024) float g_b       [(size_t)M_DIM * I_DIM];
__device__ __align__(1024) float g_mid     [(size_t)M_DIM * I_DIM];
__device__ __align__(1024) float g_xr      [(size_t)M_DIM * H_DIM];

__device__ __forceinline__ uint32_t smem_u32(const void* p) {
    uint32_t a;
    asm("{ .reg .u64 t; cvta.to.shared.u64 t, %1; cvt.u32.u64 %0, t; }" : "=r"(a) : "l"(p));
    return a;
}
#define CP_ASYNC16(dst, src) \
    asm volatile("cp.async.cg.shared.global [%0], [%1], 16;" :: "r"(dst), "l"(src) : "memory")
#define CP_COMMIT() asm volatile("cp.async.commit_group;" ::: "memory")
#define CP_WAIT1()  asm volatile("cp.async.wait_group 1;" ::: "memory")
#define CP_WAIT0()  asm volatile("cp.async.wait_group 0;" ::: "memory")

__device__ __forceinline__ float tf32r(float x) {
    uint32_t t; asm("cvt.rna.tf32.f32 %0, %1;" : "=r"(t) : "f"(x));
    return __uint_as_float(t);
}

__device__ __forceinline__ void mma_tf32(float* c, const uint32_t* a, const uint32_t* b) {
    asm volatile(
        "mma.sync.aligned.m16n8k8.row.col.f32.tf32.tf32.f32 "
        "{%0,%1,%2,%3}, {%4,%5,%6,%7}, {%8,%9}, {%0,%1,%2,%3};"
        : "+f"(c[0]), "+f"(c[1]), "+f"(c[2]), "+f"(c[3])
        : "r"(a[0]), "r"(a[1]), "r"(a[2]), "r"(a[3]), "r"(b[0]), "r"(b[1]));
}

// ---------------- elementwise kernels ----------------
__global__ void eff_kernel(const float* __restrict__ w, const float* __restrict__ su,
                           const float* __restrict__ sv, float* __restrict__ dst,
                           int indim) {
    size_t n4 = (size_t)gridDim.y * 0 + 0; (void)n4;
    size_t total4 = (size_t)blockDim.x; (void)total4;
    size_t N4 = ((size_t)indim == H_DIM) ? ((size_t)I_DIM * H_DIM / 4) : ((size_t)H_DIM * I_DIM / 4);
    for (size_t i = (size_t)blockIdx.x * blockDim.x + threadIdx.x; i < N4;
         i += (size_t)gridDim.x * blockDim.x) {
        size_t e = i * 4;
        int o = (int)(e / indim), h = (int)(e % indim);
        float4 wv = reinterpret_cast<const float4*>(w)[i];
        float sc0 = 0.f, sc1 = 0.f, sc2 = 0.f, sc3 = 0.f;
#pragma unroll
        for (int r = 0; r < 4; r++) {
            float s = su[(size_t)o * 4 + r];
            float4 vv = *reinterpret_cast<const float4*>(sv + (size_t)r * indim + h);
            sc0 += s * vv.x; sc1 += s * vv.y; sc2 += s * vv.z; sc3 += s * vv.w;
        }
        float4 ov;
        ov.x = tf32r(wv.x * sc0); ov.y = tf32r(wv.y * sc1);
        ov.z = tf32r(wv.z * sc2); ov.w = tf32r(wv.w * sc3);
        reinterpret_cast<float4*>(dst)[i] = ov;
    }
}

__global__ void round_kernel(const float* __restrict__ src, float* __restrict__ dst, size_t n4) {
    for (size_t i = (size_t)blockIdx.x * blockDim.x + threadIdx.x; i < n4;
         i += (size_t)gridDim.x * blockDim.x) {
        float4 v = reinterpret_cast<const float4*>(src)[i];
        v.x = tf32r(v.x); v.y = tf32r(v.y); v.z = tf32r(v.z); v.w = tf32r(v.w);
        reinterpret_cast<float4*>(dst)[i] = v;
    }
}

__global__ void swiglu_kernel(const float* __restrict__ a, const float* __restrict__ b,
                              float* __restrict__ m, size_t n4) {
    for (size_t i = (size_t)blockIdx.x * blockDim.x + threadIdx.x; i < n4;
         i += (size_t)gridDim.x * blockDim.x) {
        float4 av = reinterpret_cast<const float4*>(a)[i];
        float4 bv = reinterpret_cast<const float4*>(b)[i];
        float4 ov;
        ov.x = tf32r((av.x / (1.f + __expf(-av.x))) * bv.x);
        ov.y = tf32r((av.y / (1.f + __expf(-av.y))) * bv.y);
        ov.z = tf32r((av.z / (1.f + __expf(-av.z))) * bv.z);
        ov.w = tf32r((av.w / (1.f + __expf(-av.w))) * bv.w);
        reinterpret_cast<float4*>(m)[i] = ov;
    }
}

// ---------------- tf32 GEMM: C[M,N] = A[M,K] @ B[N,K]^T ----------------
// BM=128, BN=128, BK=32, 256 threads, 2x4 warp grid, 64x32 warp tiles.
// Smem rows padded to 36 floats (144B) for conflict-free fragment loads.
#define SROW 36
#define TILE_FLOATS (128 * SROW)          // 4608 floats per tile
#define BUF_FLOATS  (2 * TILE_FLOATS)     // A + B per buffer
#define SMEM_BYTES  (2 * BUF_FLOATS * 4)  // 73728 bytes, double buffered

__device__ __forceinline__ void load_tile(uint32_t sdst, const float* __restrict__ g,
                                          int stride, int tid) {
#pragma unroll
    for (int i = 0; i < 4; i++) {
        int c = tid + i * 256;
        int row = c >> 3, seg = c & 7;
        uint32_t d = sdst + (uint32_t)(row * (SROW * 4) + seg * 16);
        CP_ASYNC16(d, g + (size_t)row * stride + seg * 4);
    }
}

__global__ void __launch_bounds__(256, 2) gemm_tf32(const float* __restrict__ A,
                                                    const float* __restrict__ B,
                                                    float* __restrict__ C,
                                                    int N, int K) {
    extern __shared__ float smem[];
    uint32_t sb = smem_u32(smem);
    int tid = threadIdx.x, lane = tid & 31, wid = tid >> 5;
    int mt = blockIdx.x, nt = blockIdx.y;  // mt fastest: concurrent CTAs share B via L2
    int warp_m = wid & 1, warp_n = wid >> 1;
    int g = lane >> 2, t = lane & 3;
    const float* Ag = A + (size_t)mt * 128 * K;
    const float* Bg = B + (size_t)nt * 128 * K;
    const int KT = K / 32;

    float acc[4][4][4];
#pragma unroll
    for (int i = 0; i < 4; i++)
#pragma unroll
        for (int j = 0; j < 4; j++)
#pragma unroll
            for (int q = 0; q < 4; q++) acc[i][j][q] = 0.f;

    // prologue
    load_tile(sb, Ag, K, tid);
    load_tile(sb + TILE_FLOATS * 4, Bg, K, tid);
    CP_COMMIT();

    for (int kt = 0; kt < KT; kt++) {
        int buf = kt & 1;
        if (kt + 1 < KT) {
            uint32_t nb = sb + (buf ^ 1) * (BUF_FLOATS * 4);
            load_tile(nb, Ag + (kt + 1) * 32, K, tid);
            load_tile(nb + TILE_FLOATS * 4, Bg + (kt + 1) * 32, K, tid);
            CP_COMMIT(); CP_WAIT1();
        } else {
            CP_WAIT0();
        }
        __syncthreads();

        const uint32_t* As = (const uint32_t*)(smem + buf * BUF_FLOATS);
        const uint32_t* Bs = As + TILE_FLOATS;
#pragma unroll
        for (int kk = 0; kk < 4; kk++) {
            int col = kk * 8 + t;
            uint32_t af[4][4], bf[4][2];
#pragma unroll
            for (int i = 0; i < 4; i++) {
                int r0 = warp_m * 64 + i * 16 + g;
                af[i][0] = As[r0 * SROW + col];
                af[i][1] = As[(r0 + 8) * SROW + col];
                af[i][2] = As[r0 * SROW + col + 4];
                af[i][3] = As[(r0 + 8) * SROW + col + 4];
            }
#pragma unroll
            for (int j = 0; j < 4; j++) {
                int n0 = warp_n * 32 + j * 8 + g;
                bf[j][0] = Bs[n0 * SROW + col];
                bf[j][1] = Bs[n0 * SROW + col + 4];
            }
#pragma unroll
            for (int i = 0; i < 4; i++)
#pragma unroll
                for (int j = 0; j < 4; j++) mma_tf32(acc[i][j], af[i], bf[j]);
        }
        __syncthreads();
    }

    // epilogue: direct fp32 store
#pragma unroll
    for (int i = 0; i < 4; i++) {
        int row0 = mt * 128 + warp_m * 64 + i * 16 + g;
#pragma unroll
        for (int j = 0; j < 4; j++) {
            int cc = nt * 128 + warp_n * 32 + j * 8 + t * 2;
            float2* p0 = (float2*)(C + (size_t)row0 * N + cc);
            float2* p1 = (float2*)(C + (size_t)(row0 + 8) * N + cc);
            *p0 = make_float2(acc[i][j][0], acc[i][j][1]);
            *p1 = make_float2(acc[i][j][2], acc[i][j][3]);
        }
    }
}

// ---------------- launch ----------------
extern "C" void kernel_launch(void* const* d_in, const int* in_sizes, int n_in,
                              void* d_out, int out_size) {
    (void)in_sizes; (void)n_in; (void)out_size;
    const float* x       = (const float*)d_in[0];
    const float* gate_w  = (const float*)d_in[1];
    const float* gate_su = (const float*)d_in[2];
    const float* gate_sv = (const float*)d_in[3];
    const float* up_w    = (const float*)d_in[4];
    const float* up_su   = (const float*)d_in[5];
    const float* up_sv   = (const float*)d_in[6];
    const float* down_w  = (const float*)d_in[7];
    const float* down_su = (const float*)d_in[8];
    const float* down_sv = (const float*)d_in[9];
    float* out = (float*)d_out;

    void *pg, *pu, *pd, *pa, *pb, *pm, *pxr;
    cudaGetSymbolAddress(&pg, g_gate_eff);
    cudaGetSymbolAddress(&pu, g_up_eff);
    cudaGetSymbolAddress(&pd, g_down_eff);
    cudaGetSymbolAddress(&pa, g_a);
    cudaGetSymbolAddress(&pb, g_b);
    cudaGetSymbolAddress(&pm, g_mid);
    cudaGetSymbolAddress(&pxr, g_xr);

    cudaFuncSetAttribute(gemm_tf32, cudaFuncAttributeMaxDynamicSharedMemorySize, SMEM_BYTES);

    eff_kernel<<<1184, 256>>>(gate_w, gate_su, gate_sv, (float*)pg, H_DIM);
    eff_kernel<<<1184, 256>>>(up_w,   up_su,   up_sv,   (float*)pu, H_DIM);
    eff_kernel<<<1184, 256>>>(down_w, down_su, down_sv, (float*)pd, I_DIM);
    round_kernel<<<592, 256>>>(x, (float*)pxr, (size_t)M_DIM * H_DIM / 4);

    // gate: [1024,4096] @ [14336,4096]^T -> g_a
    gemm_tf32<<<dim3(M_DIM / 128, I_DIM / 128), 256, SMEM_BYTES>>>(
        (const float*)pxr, (const float*)pg, (float*)pa, I_DIM, H_DIM);
    // up -> g_b
    gemm_tf32<<<dim3(M_DIM / 128, I_DIM / 128), 256, SMEM_BYTES>>>(
        (const float*)pxr, (const float*)pu, (float*)pb, I_DIM, H_DIM);
    // swiglu -> g_mid (tf32-rounded)
    swiglu_kernel<<<1184, 256>>>((const float*)pa, (const float*)pb, (float*)pm,
                                 (size_t)M_DIM * I_DIM / 4);
    // down: [1024,14336] @ [4096,14336]^T -> out
    gemm_tf32<<<dim3(M_DIM / 128, H_DIM / 128), 256, SMEM_BYTES>>>(
        (const float*)pm, (const float*)pd, out, H_DIM, I_DIM);
}

// round 6
// speedup vs baseline: 1.1221x; 1.1221x over previous
#include <cuda_runtime.h>
#include <cuda_bf16.h>
#include <cstdint>
#include <cstddef>

#define H_DIM 4096
#define I_DIM 14336
#define M_DIM 1024

__device__ __align__(1024) float g_gate_eff[(size_t)I_DIM * H_DIM];
__device__ __align__(1024) float g_up_eff  [(size_t)I_DIM * H_DIM];
__device__ __align__(1024) float g_down_eff[(size_t)H_DIM * I_DIM];
__device__ __align__(1024) float g_mid     [(size_t)M_DIM * I_DIM];
__device__ __align__(1024) float g_xr      [(size_t)M_DIM * H_DIM];

__device__ __forceinline__ uint32_t smem_u32(const void* p) {
    uint32_t a;
    asm("{ .reg .u64 t; cvta.to.shared.u64 t, %1; cvt.u32.u64 %0, t; }" : "=r"(a) : "l"(p));
    return a;
}
#define CP_ASYNC16(dst, src) \
    asm volatile("cp.async.cg.shared.global [%0], [%1], 16;" :: "r"(dst), "l"(src) : "memory")
#define CP_COMMIT() asm volatile("cp.async.commit_group;" ::: "memory")
#define CP_WAIT1()  asm volatile("cp.async.wait_group 1;" ::: "memory")
#define CP_WAIT0()  asm volatile("cp.async.wait_group 0;" ::: "memory")

__device__ __forceinline__ float tf32r(float x) {
    uint32_t t; asm("cvt.rna.tf32.f32 %0, %1;" : "=r"(t) : "f"(x));
    return __uint_as_float(t);
}

__device__ __forceinline__ void mma8(float* c, uint32_t a0, uint32_t a1, uint32_t a2,
                                     uint32_t a3, uint32_t b0, uint32_t b1) {
    asm volatile(
        "mma.sync.aligned.m16n8k8.row.col.f32.tf32.tf32.f32 "
        "{%0,%1,%2,%3}, {%4,%5,%6,%7}, {%8,%9}, {%0,%1,%2,%3};"
        : "+f"(c[0]), "+f"(c[1]), "+f"(c[2]), "+f"(c[3])
        : "r"(a0), "r"(a1), "r"(a2), "r"(a3), "r"(b0), "r"(b1));
}

__device__ __forceinline__ float silu_mul(float g, float u) {
    return tf32r((g / (1.f + __expf(-g))) * u);
}

// ---------------- elementwise kernels ----------------
__global__ void eff_kernel(const float* __restrict__ w, const float* __restrict__ su,
                           const float* __restrict__ sv, float* __restrict__ dst,
                           int indim, size_t n4) {
    for (size_t i = (size_t)blockIdx.x * blockDim.x + threadIdx.x; i < n4;
         i += (size_t)gridDim.x * blockDim.x) {
        size_t e = i * 4;
        int o = (int)(e / indim), h = (int)(e % indim);
        float4 wv = reinterpret_cast<const float4*>(w)[i];
        float sc0 = 0.f, sc1 = 0.f, sc2 = 0.f, sc3 = 0.f;
#pragma unroll
        for (int r = 0; r < 4; r++) {
            float s = su[(size_t)o * 4 + r];
            float4 vv = *reinterpret_cast<const float4*>(sv + (size_t)r * indim + h);
            sc0 += s * vv.x; sc1 += s * vv.y; sc2 += s * vv.z; sc3 += s * vv.w;
        }
        float4 ov;
        ov.x = tf32r(wv.x * sc0); ov.y = tf32r(wv.y * sc1);
        ov.z = tf32r(wv.z * sc2); ov.w = tf32r(wv.w * sc3);
        reinterpret_cast<float4*>(dst)[i] = ov;
    }
}

__global__ void round_kernel(const float* __restrict__ src, float* __restrict__ dst, size_t n4) {
    for (size_t i = (size_t)blockIdx.x * blockDim.x + threadIdx.x; i < n4;
         i += (size_t)gridDim.x * blockDim.x) {
        float4 v = reinterpret_cast<const float4*>(src)[i];
        v.x = tf32r(v.x); v.y = tf32r(v.y); v.z = tf32r(v.z); v.w = tf32r(v.w);
        reinterpret_cast<float4*>(dst)[i] = v;
    }
}

// ---------------- GEMM tiles ----------------
// BM=BN=128, BK=32, 256 threads, 2x4 warp grid, 64x32 warp tiles.
// SROW=40 floats (160B): LDS.64 fragment loads are bank-conflict-free.
#define SROW 40
#define TILEF (128 * SROW)
#define GU_BUF (3 * TILEF)
#define GU_SMEM (2 * GU_BUF * 4)   // 122880 B
#define DN_BUF (2 * TILEF)
#define DN_SMEM (2 * DN_BUF * 4)   // 81920 B

__device__ __forceinline__ void load_tile(uint32_t sdst, const float* __restrict__ g,
                                          int stride, int tid) {
#pragma unroll
    for (int i = 0; i < 4; i++) {
        int c = tid + i * 256;
        int row = c >> 3, seg = c & 7;
        uint32_t d = sdst + (uint32_t)(row * (SROW * 4) + seg * 16);
        CP_ASYNC16(d, g + (size_t)row * stride + seg * 4);
    }
}

// ---------------- fused gate+up GEMM + SwiGLU -> g_mid ----------------
__global__ void __launch_bounds__(256, 1) gemm_gateup() {
    extern __shared__ float smem[];
    uint32_t sb = smem_u32(smem);
    int tid = threadIdx.x, lane = tid & 31, wid = tid >> 5;
    int mt = blockIdx.x, nt = blockIdx.y;
    int warp_m = wid & 1, warp_n = wid >> 1;
    int g = lane >> 2, t = lane & 3;
    const float* Ag = g_xr + (size_t)mt * 128 * H_DIM;
    const float* Gg = g_gate_eff + (size_t)nt * 128 * H_DIM;
    const float* Ug = g_up_eff + (size_t)nt * 128 * H_DIM;
    const int KT = H_DIM / 32;

    float accg[4][4][4] = {}, accu[4][4][4] = {};

    load_tile(sb, Ag, H_DIM, tid);
    load_tile(sb + TILEF * 4, Gg, H_DIM, tid);
    load_tile(sb + 2 * TILEF * 4, Ug, H_DIM, tid);
    CP_COMMIT();

    for (int kt = 0; kt < KT; kt++) {
        int buf = kt & 1;
        if (kt + 1 < KT) {
            uint32_t nb = sb + (buf ^ 1) * (GU_BUF * 4);
            int k0 = (kt + 1) * 32;
            load_tile(nb, Ag + k0, H_DIM, tid);
            load_tile(nb + TILEF * 4, Gg + k0, H_DIM, tid);
            load_tile(nb + 2 * TILEF * 4, Ug + k0, H_DIM, tid);
            CP_COMMIT(); CP_WAIT1();
        } else CP_WAIT0();
        __syncthreads();

        const float* As = smem + buf * GU_BUF;
        const float* Gs = As + TILEF;
        const float* Us = Gs + TILEF;
#pragma unroll
        for (int kk = 0; kk < 4; kk++) {
            int col2 = kk * 8 + 2 * t;
            uint2 alo[4], ahi[4], bg[4], bu[4];
#pragma unroll
            for (int i = 0; i < 4; i++) {
                int r0 = warp_m * 64 + i * 16 + g;
                alo[i] = *(const uint2*)(As + r0 * SROW + col2);
                ahi[i] = *(const uint2*)(As + (r0 + 8) * SROW + col2);
            }
#pragma unroll
            for (int j = 0; j < 4; j++) {
                int n0 = warp_n * 32 + j * 8 + g;
                bg[j] = *(const uint2*)(Gs + n0 * SROW + col2);
                bu[j] = *(const uint2*)(Us + n0 * SROW + col2);
            }
#pragma unroll
            for (int i = 0; i < 4; i++)
#pragma unroll
                for (int j = 0; j < 4; j++) {
                    mma8(accg[i][j], alo[i].x, ahi[i].x, alo[i].y, ahi[i].y, bg[j].x, bg[j].y);
                    mma8(accu[i][j], alo[i].x, ahi[i].x, alo[i].y, ahi[i].y, bu[j].x, bu[j].y);
                }
        }
        __syncthreads();
    }

    // SwiGLU epilogue -> g_mid (tf32-rounded for the down GEMM)
#pragma unroll
    for (int i = 0; i < 4; i++) {
        int r0 = mt * 128 + warp_m * 64 + i * 16 + g;
#pragma unroll
        for (int j = 0; j < 4; j++) {
            int cc = nt * 128 + warp_n * 32 + j * 8 + t * 2;
            float v0 = silu_mul(accg[i][j][0], accu[i][j][0]);
            float v1 = silu_mul(accg[i][j][1], accu[i][j][1]);
            float v2 = silu_mul(accg[i][j][2], accu[i][j][2]);
            float v3 = silu_mul(accg[i][j][3], accu[i][j][3]);
            *(float2*)(g_mid + (size_t)r0 * I_DIM + cc) = make_float2(v0, v1);
            *(float2*)(g_mid + (size_t)(r0 + 8) * I_DIM + cc) = make_float2(v2, v3);
        }
    }
}

// ---------------- down GEMM -> out ----------------
__global__ void __launch_bounds__(256, 2) gemm_down(float* __restrict__ out) {
    extern __shared__ float smem[];
    uint32_t sb = smem_u32(smem);
    int tid = threadIdx.x, lane = tid & 31, wid = tid >> 5;
    int mt = blockIdx.x, nt = blockIdx.y;
    int warp_m = wid & 1, warp_n = wid >> 1;
    int g = lane >> 2, t = lane & 3;
    const float* Ag = g_mid + (size_t)mt * 128 * I_DIM;
    const float* Bg = g_down_eff + (size_t)nt * 128 * I_DIM;
    const int KT = I_DIM / 32;

    float acc[4][4][4] = {};

    load_tile(sb, Ag, I_DIM, tid);
    load_tile(sb + TILEF * 4, Bg, I_DIM, tid);
    CP_COMMIT();

    for (int kt = 0; kt < KT; kt++) {
        int buf = kt & 1;
        if (kt + 1 < KT) {
            uint32_t nb = sb + (buf ^ 1) * (DN_BUF * 4);
            int k0 = (kt + 1) * 32;
            load_tile(nb, Ag + k0, I_DIM, tid);
            load_tile(nb + TILEF * 4, Bg + k0, I_DIM, tid);
            CP_COMMIT(); CP_WAIT1();
        } else CP_WAIT0();
        __syncthreads();

        const float* As = smem + buf * DN_BUF;
        const float* Bs = As + TILEF;
#pragma unroll
        for (int kk = 0; kk < 4; kk++) {
            int col2 = kk * 8 + 2 * t;
            uint2 alo[4], ahi[4], bf[4];
#pragma unroll
            for (int i = 0; i < 4; i++) {
                int r0 = warp_m * 64 + i * 16 + g;
                alo[i] = *(const uint2*)(As + r0 * SROW + col2);
                ahi[i] = *(const uint2*)(As + (r0 + 8) * SROW + col2);
            }
#pragma unroll
            for (int j = 0; j < 4; j++) {
                int n0 = warp_n * 32 + j * 8 + g;
                bf[j] = *(const uint2*)(Bs + n0 * SROW + col2);
            }
#pragma unroll
            for (int i = 0; i < 4; i++)
#pragma unroll
                for (int j = 0; j < 4; j++)
                    mma8(acc[i][j], alo[i].x, ahi[i].x, alo[i].y, ahi[i].y, bf[j].x, bf[j].y);
        }
        __syncthreads();
    }

#pragma unroll
    for (int i = 0; i < 4; i++) {
        int r0 = mt * 128 + warp_m * 64 + i * 16 + g;
#pragma unroll
        for (int j = 0; j < 4; j++) {
            int cc = nt * 128 + warp_n * 32 + j * 8 + t * 2;
            *(float2*)(out + (size_t)r0 * H_DIM + cc) = make_float2(acc[i][j][0], acc[i][j][1]);
            *(float2*)(out + (size_t)(r0 + 8) * H_DIM + cc) = make_float2(acc[i][j][2], acc[i][j][3]);
        }
    }
}

// ---------------- launch ----------------
extern "C" void kernel_launch(void* const* d_in, const int* in_sizes, int n_in,
                              void* d_out, int out_size) {
    (void)in_sizes; (void)n_in; (void)out_size;
    const float* x       = (const float*)d_in[0];
    const float* gate_w  = (const float*)d_in[1];
    const float* gate_su = (const float*)d_in[2];
    const float* gate_sv = (const float*)d_in[3];
    const float* up_w    = (const float*)d_in[4];
    const float* up_su   = (const float*)d_in[5];
    const float* up_sv   = (const float*)d_in[6];
    const float* down_w  = (const float*)d_in[7];
    const float* down_su = (const float*)d_in[8];
    const float* down_sv = (const float*)d_in[9];
    float* out = (float*)d_out;

    void *pg, *pu, *pd, *pxr;
    cudaGetSymbolAddress(&pg, g_gate_eff);
    cudaGetSymbolAddress(&pu, g_up_eff);
    cudaGetSymbolAddress(&pd, g_down_eff);
    cudaGetSymbolAddress(&pxr, g_xr);

    cudaFuncSetAttribute(gemm_gateup, cudaFuncAttributeMaxDynamicSharedMemorySize, GU_SMEM);
    cudaFuncSetAttribute(gemm_down,   cudaFuncAttributeMaxDynamicSharedMemorySize, DN_SMEM);

    size_t nw = (size_t)I_DIM * H_DIM / 4;
    eff_kernel<<<1184, 256>>>(gate_w, gate_su, gate_sv, (float*)pg, H_DIM, nw);
    eff_kernel<<<1184, 256>>>(up_w,   up_su,   up_sv,   (float*)pu, H_DIM, nw);
    eff_kernel<<<1184, 256>>>(down_w, down_su, down_sv, (float*)pd, I_DIM, nw);
    round_kernel<<<592, 256>>>(x, (float*)pxr, (size_t)M_DIM * H_DIM / 4);

    gemm_gateup<<<dim3(M_DIM / 128, I_DIM / 128), 256, GU_SMEM>>>();
    gemm_down<<<dim3(M_DIM / 128, H_DIM / 128), 256, DN_SMEM>>>(out);
}

// round 7
// speedup vs baseline: 1.1452x; 1.0206x over previous
#include <cuda_runtime.h>
#include <cuda_bf16.h>
#include <cstdint>
#include <cstddef>

#define H_DIM 4096
#define I_DIM 14336
#define M_DIM 1024

__device__ __align__(1024) float g_gate_eff[(size_t)I_DIM * H_DIM];
__device__ __align__(1024) float g_up_eff  [(size_t)I_DIM * H_DIM];
__device__ __align__(1024) float g_down_eff[(size_t)H_DIM * I_DIM];
__device__ __align__(1024) float g_mid     [(size_t)M_DIM * I_DIM];
__device__ __align__(1024) float g_xr      [(size_t)M_DIM * H_DIM];

__device__ __forceinline__ uint32_t smem_u32(const void* p) {
    uint32_t a;
    asm("{ .reg .u64 t; cvta.to.shared.u64 t, %1; cvt.u32.u64 %0, t; }" : "=r"(a) : "l"(p));
    return a;
}
#define CP_ASYNC16(dst, src) \
    asm volatile("cp.async.cg.shared.global [%0], [%1], 16;" :: "r"(dst), "l"(src) : "memory")
#define CP_COMMIT() asm volatile("cp.async.commit_group;" ::: "memory")
#define CP_WAIT1()  asm volatile("cp.async.wait_group 1;" ::: "memory")
#define CP_WAIT0()  asm volatile("cp.async.wait_group 0;" ::: "memory")

__device__ __forceinline__ float tf32r(float x) {
    uint32_t t; asm("cvt.rna.tf32.f32 %0, %1;" : "=r"(t) : "f"(x));
    return __uint_as_float(t);
}

__device__ __forceinline__ void mma8(float* c, uint32_t a0, uint32_t a1, uint32_t a2,
                                     uint32_t a3, uint32_t b0, uint32_t b1) {
    asm volatile(
        "mma.sync.aligned.m16n8k8.row.col.f32.tf32.tf32.f32 "
        "{%0,%1,%2,%3}, {%4,%5,%6,%7}, {%8,%9}, {%0,%1,%2,%3};"
        : "+f"(c[0]), "+f"(c[1]), "+f"(c[2]), "+f"(c[3])
        : "r"(a0), "r"(a1), "r"(a2), "r"(a3), "r"(b0), "r"(b1));
}

__device__ __forceinline__ float silu_mul(float g, float u) {
    return tf32r((g / (1.f + __expf(-g))) * u);
}

// ---------------- elementwise kernels ----------------
__global__ void eff_kernel(const float* __restrict__ w, const float* __restrict__ su,
                           const float* __restrict__ sv, float* __restrict__ dst,
                           int indim, size_t n4) {
    for (size_t i = (size_t)blockIdx.x * blockDim.x + threadIdx.x; i < n4;
         i += (size_t)gridDim.x * blockDim.x) {
        size_t e = i * 4;
        int o = (int)(e / indim), h = (int)(e % indim);
        float4 wv = reinterpret_cast<const float4*>(w)[i];
        float sc0 = 0.f, sc1 = 0.f, sc2 = 0.f, sc3 = 0.f;
#pragma unroll
        for (int r = 0; r < 4; r++) {
            float s = su[(size_t)o * 4 + r];
            float4 vv = *reinterpret_cast<const float4*>(sv + (size_t)r * indim + h);
            sc0 += s * vv.x; sc1 += s * vv.y; sc2 += s * vv.z; sc3 += s * vv.w;
        }
        float4 ov;
        ov.x = tf32r(wv.x * sc0); ov.y = tf32r(wv.y * sc1);
        ov.z = tf32r(wv.z * sc2); ov.w = tf32r(wv.w * sc3);
        reinterpret_cast<float4*>(dst)[i] = ov;
    }
}

__global__ void round_kernel(const float* __restrict__ src, float* __restrict__ dst, size_t n4) {
    for (size_t i = (size_t)blockIdx.x * blockDim.x + threadIdx.x; i < n4;
         i += (size_t)gridDim.x * blockDim.x) {
        float4 v = reinterpret_cast<const float4*>(src)[i];
        v.x = tf32r(v.x); v.y = tf32r(v.y); v.z = tf32r(v.z); v.w = tf32r(v.w);
        reinterpret_cast<float4*>(dst)[i] = v;
    }
}

// ---------------- GEMM tiling ----------------
#define SROW 40
#define TILEF128 (128 * SROW)
#define TILEF64  (64 * SROW)
// gateup: BM=128, BN=64, BK=32; stage = A(128) + G(64) + U(64) rows
#define GU_STAGE (256 * SROW)
#define GU_SMEM (2 * GU_STAGE * 4)      // 81920 B -> 2 CTAs/SM
// down: BM=128, BN=128, BK=32
#define DN_BUF (2 * TILEF128)
#define DN_SMEM (2 * DN_BUF * 4)        // 81920 B -> 2 CTAs/SM

__device__ __forceinline__ void load_tile128(uint32_t sdst, const float* __restrict__ g,
                                             int stride, int tid) {
#pragma unroll
    for (int i = 0; i < 4; i++) {
        int c = tid + i * 256;
        int row = c >> 3, seg = c & 7;
        uint32_t d = sdst + (uint32_t)(row * (SROW * 4) + seg * 16);
        CP_ASYNC16(d, g + (size_t)row * stride + seg * 4);
    }
}
__device__ __forceinline__ void load_tile64(uint32_t sdst, const float* __restrict__ g,
                                            int stride, int tid) {
#pragma unroll
    for (int i = 0; i < 2; i++) {
        int c = tid + i * 256;
        int row = c >> 3, seg = c & 7;
        uint32_t d = sdst + (uint32_t)(row * (SROW * 4) + seg * 16);
        CP_ASYNC16(d, g + (size_t)row * stride + seg * 4);
    }
}

// ---------------- fused gate+up GEMM + SwiGLU -> g_mid ----------------
// 2x4 warp grid; warp tile 64x16 (i=0..3 m16 tiles, j=0..1 n8 tiles) for both G and U.
__global__ void __launch_bounds__(256, 2) gemm_gateup() {
    extern __shared__ float smem[];
    uint32_t sb = smem_u32(smem);
    int tid = threadIdx.x, lane = tid & 31, wid = tid >> 5;
    int mt = blockIdx.x, nt = blockIdx.y;
    int warp_m = wid & 1, warp_n = wid >> 1;
    int g = lane >> 2, t = lane & 3;
    const float* Ag = g_xr + (size_t)mt * 128 * H_DIM;
    const float* Gg = g_gate_eff + (size_t)nt * 64 * H_DIM;
    const float* Ug = g_up_eff + (size_t)nt * 64 * H_DIM;
    const int KT = H_DIM / 32;

    float accg[4][2][4] = {}, accu[4][2][4] = {};

    load_tile128(sb, Ag, H_DIM, tid);
    load_tile64(sb + TILEF128 * 4, Gg, H_DIM, tid);
    load_tile64(sb + (TILEF128 + TILEF64) * 4, Ug, H_DIM, tid);
    CP_COMMIT();

    for (int kt = 0; kt < KT; kt++) {
        int buf = kt & 1;
        if (kt + 1 < KT) {
            uint32_t nb = sb + (buf ^ 1) * (GU_STAGE * 4);
            int k0 = (kt + 1) * 32;
            load_tile128(nb, Ag + k0, H_DIM, tid);
            load_tile64(nb + TILEF128 * 4, Gg + k0, H_DIM, tid);
            load_tile64(nb + (TILEF128 + TILEF64) * 4, Ug + k0, H_DIM, tid);
            CP_COMMIT(); CP_WAIT1();
        } else CP_WAIT0();
        __syncthreads();

        const float* As = smem + buf * GU_STAGE;
        const float* Gs = As + TILEF128;
        const float* Us = Gs + TILEF64;
#pragma unroll
        for (int kk = 0; kk < 4; kk++) {
            int col2 = kk * 8 + 2 * t;
            uint2 alo[4], ahi[4], bg[2], bu[2];
#pragma unroll
            for (int i = 0; i < 4; i++) {
                int r0 = warp_m * 64 + i * 16 + g;
                alo[i] = *(const uint2*)(As + r0 * SROW + col2);
                ahi[i] = *(const uint2*)(As + (r0 + 8) * SROW + col2);
            }
#pragma unroll
            for (int j = 0; j < 2; j++) {
                int n0 = warp_n * 16 + j * 8 + g;
                bg[j] = *(const uint2*)(Gs + n0 * SROW + col2);
                bu[j] = *(const uint2*)(Us + n0 * SROW + col2);
            }
#pragma unroll
            for (int i = 0; i < 4; i++)
#pragma unroll
                for (int j = 0; j < 2; j++) {
                    mma8(accg[i][j], alo[i].x, ahi[i].x, alo[i].y, ahi[i].y, bg[j].x, bg[j].y);
                    mma8(accu[i][j], alo[i].x, ahi[i].x, alo[i].y, ahi[i].y, bu[j].x, bu[j].y);
                }
        }
        __syncthreads();
    }

#pragma unroll
    for (int i = 0; i < 4; i++) {
        int r0 = mt * 128 + warp_m * 64 + i * 16 + g;
#pragma unroll
        for (int j = 0; j < 2; j++) {
            int cc = nt * 64 + warp_n * 16 + j * 8 + t * 2;
            float v0 = silu_mul(accg[i][j][0], accu[i][j][0]);
            float v1 = silu_mul(accg[i][j][1], accu[i][j][1]);
            float v2 = silu_mul(accg[i][j][2], accu[i][j][2]);
            float v3 = silu_mul(accg[i][j][3], accu[i][j][3]);
            *(float2*)(g_mid + (size_t)r0 * I_DIM + cc) = make_float2(v0, v1);
            *(float2*)(g_mid + (size_t)(r0 + 8) * I_DIM + cc) = make_float2(v2, v3);
        }
    }
}

// ---------------- down GEMM -> out ----------------
__global__ void __launch_bounds__(256, 2) gemm_down(float* __restrict__ out) {
    extern __shared__ float smem[];
    uint32_t sb = smem_u32(smem);
    int tid = threadIdx.x, lane = tid & 31, wid = tid >> 5;
    int mt = blockIdx.x, nt = blockIdx.y;
    int warp_m = wid & 1, warp_n = wid >> 1;
    int g = lane >> 2, t = lane & 3;
    const float* Ag = g_mid + (size_t)mt * 128 * I_DIM;
    const float* Bg = g_down_eff + (size_t)nt * 128 * I_DIM;
    const int KT = I_DIM / 32;

    float acc[4][4][4] = {};

    load_tile128(sb, Ag, I_DIM, tid);
    load_tile128(sb + TILEF128 * 4, Bg, I_DIM, tid);
    CP_COMMIT();

    for (int kt = 0; kt < KT; kt++) {
        int buf = kt & 1;
        if (kt + 1 < KT) {
            uint32_t nb = sb + (buf ^ 1) * (DN_BUF * 4);
            int k0 = (kt + 1) * 32;
            load_tile128(nb, Ag + k0, I_DIM, tid);
            load_tile128(nb + TILEF128 * 4, Bg + k0, I_DIM, tid);
            CP_COMMIT(); CP_WAIT1();
        } else CP_WAIT0();
        __syncthreads();

        const float* As = smem + buf * DN_BUF;
        const float* Bs = As + TILEF128;
#pragma unroll
        for (int kk = 0; kk < 4; kk++) {
            int col2 = kk * 8 + 2 * t;
            uint2 alo[4], ahi[4], bf[4];
#pragma unroll
            for (int i = 0; i < 4; i++) {
                int r0 = warp_m * 64 + i * 16 + g;
                alo[i] = *(const uint2*)(As + r0 * SROW + col2);
                ahi[i] = *(const uint2*)(As + (r0 + 8) * SROW + col2);
            }
#pragma unroll
            for (int j = 0; j < 4; j++) {
                int n0 = warp_n * 32 + j * 8 + g;
                bf[j] = *(const uint2*)(Bs + n0 * SROW + col2);
            }
#pragma unroll
            for (int i = 0; i < 4; i++)
#pragma unroll
                for (int j = 0; j < 4; j++)
                    mma8(acc[i][j], alo[i].x, ahi[i].x, alo[i].y, ahi[i].y, bf[j].x, bf[j].y);
        }
        __syncthreads();
    }

#pragma unroll
    for (int i = 0; i < 4; i++) {
        int r0 = mt * 128 + warp_m * 64 + i * 16 + g;
#pragma unroll
        for (int j = 0; j < 4; j++) {
            int cc = nt * 128 + warp_n * 32 + j * 8 + t * 2;
            *(float2*)(out + (size_t)r0 * H_DIM + cc) = make_float2(acc[i][j][0], acc[i][j][1]);
            *(float2*)(out + (size_t)(r0 + 8) * H_DIM + cc) = make_float2(acc[i][j][2], acc[i][j][3]);
        }
    }
}

// ---------------- launch ----------------
extern "C" void kernel_launch(void* const* d_in, const int* in_sizes, int n_in,
                              void* d_out, int out_size) {
    (void)in_sizes; (void)n_in; (void)out_size;
    const float* x       = (const float*)d_in[0];
    const float* gate_w  = (const float*)d_in[1];
    const float* gate_su = (const float*)d_in[2];
    const float* gate_sv = (const float*)d_in[3];
    const float* up_w    = (const float*)d_in[4];
    const float* up_su   = (const float*)d_in[5];
    const float* up_sv   = (const float*)d_in[6];
    const float* down_w  = (const float*)d_in[7];
    const float* down_su = (const float*)d_in[8];
    const float* down_sv = (const float*)d_in[9];
    float* out = (float*)d_out;

    void *pg, *pu, *pd, *pxr;
    cudaGetSymbolAddress(&pg, g_gate_eff);
    cudaGetSymbolAddress(&pu, g_up_eff);
    cudaGetSymbolAddress(&pd, g_down_eff);
    cudaGetSymbolAddress(&pxr, g_xr);

    cudaFuncSetAttribute(gemm_gateup, cudaFuncAttributeMaxDynamicSharedMemorySize, GU_SMEM);
    cudaFuncSetAttribute(gemm_down,   cudaFuncAttributeMaxDynamicSharedMemorySize, DN_SMEM);

    size_t nw = (size_t)I_DIM * H_DIM / 4;
    eff_kernel<<<1184, 256>>>(gate_w, gate_su, gate_sv, (float*)pg, H_DIM, nw);
    eff_kernel<<<1184, 256>>>(up_w,   up_su,   up_sv,   (float*)pu, H_DIM, nw);
    eff_kernel<<<1184, 256>>>(down_w, down_su, down_sv, (float*)pd, I_DIM, nw);
    round_kernel<<<592, 256>>>(x, (float*)pxr, (size_t)M_DIM * H_DIM / 4);

    gemm_gateup<<<dim3(M_DIM / 128, I_DIM / 64), 256, GU_SMEM>>>();
    gemm_down<<<dim3(M_DIM / 128, H_DIM / 128), 256, DN_SMEM>>>(out);
}